// round 2
// baseline (speedup 1.0000x reference)
#include <cuda_runtime.h>
#include <math.h>

#define NMOL 16
#define NATOM 64
#define RADF 64         // 4 species * 16 radial shifts
#define ANGF 320        // 10 pairs * 4 SHF_A * 8 SHF_Z
#define FEAT 384
#define RCR 5.2f
#define RCA 3.5f

__constant__ int c_triu[4][4] = {
    {0,1,2,3},
    {1,4,5,6},
    {2,5,7,8},
    {3,6,8,9}
};

// cos/sin of SHF_Z[z] = pi/16 * (1 + 2z), z = 0..7
__constant__ float c_cz[8] = {
     0.980785280403230449f,  0.831469612302545237f,  0.555570233019602225f,
     0.195090322016128268f, -0.195090322016128268f, -0.555570233019602225f,
    -0.831469612302545237f, -0.980785280403230449f
};
__constant__ float c_sz[8] = {
     0.195090322016128268f,  0.555570233019602225f,  0.831469612302545237f,
     0.980785280403230449f,  0.980785280403230449f,  0.831469612302545237f,
     0.555570233019602225f,  0.195090322016128268f
};

__device__ __forceinline__ float pow32(float u) {
    // u^32 via 5 squarings; clamp tiny negative from rounding (ref value >= 0)
    u = fmaxf(u, 0.0f);
    u = u * u;   // ^2
    u = u * u;   // ^4
    u = u * u;   // ^8
    u = u * u;   // ^16
    u = u * u;   // ^32
    return u;
}

__global__ __launch_bounds__(NATOM)
void aev_kernel(const int* __restrict__ species,
                const float* __restrict__ coords,
                float* __restrict__ out,
                int aev_base,          // 1024 if species is part of output, else 0
                int write_species)
{
    const int atom = blockIdx.x;           // 0 .. NMOL*NATOM-1
    const int n = atom >> 6;
    const int i = atom & 63;
    const int tid = threadIdx.x;

    __shared__ float s_x[NATOM], s_y[NATOM], s_z[NATOM];
    __shared__ float s_dx[NATOM], s_dy[NATOM], s_dz[NATOM];
    __shared__ float s_d[NATOM], s_fca[NATOM];
    __shared__ int   s_spec[NATOM];
    __shared__ int   s_nb[NATOM];
    __shared__ int   s_cnt;
    __shared__ float s_rad[RADF];
    __shared__ float s_ang[ANGF];

    // ---- stage molecule into SMEM ----
    const float* cb = coords + (size_t)n * NATOM * 3;
    s_x[tid] = cb[tid * 3 + 0];
    s_y[tid] = cb[tid * 3 + 1];
    s_z[tid] = cb[tid * 3 + 2];
    s_spec[tid] = species[n * NATOM + tid];
    if (tid == 0) s_cnt = 0;
    s_rad[tid] = 0.0f;
    #pragma unroll
    for (int f = tid; f < ANGF; f += NATOM) s_ang[f] = 0.0f;
    __syncthreads();

    // ---- per-neighbor geometry (thread tid == neighbor j) ----
    const float dx = s_x[tid] - s_x[i];
    const float dy = s_y[tid] - s_y[i];
    const float dz = s_z[tid] - s_z[i];
    const float d  = sqrtf(dx * dx + dy * dy + dz * dz);
    s_dx[tid] = dx; s_dy[tid] = dy; s_dz[tid] = dz;
    s_d[tid]  = d;
    s_fca[tid] = 0.5f * cosf((float)M_PI * d / RCA) + 0.5f;
    const bool self = (tid == i);

    // ---- radial term ----
    if (!self && d <= RCR) {
        const float fc = 0.5f * cosf((float)M_PI * d / RCR) + 0.5f;
        const int base = s_spec[tid] * 16;
        #pragma unroll
        for (int r = 0; r < 16; r++) {
            const float sh = 0.9f + 0.26875f * (float)r;
            const float t = d - sh;
            atomicAdd(&s_rad[base + r], 0.25f * expf(-16.0f * t * t) * fc);
        }
    }

    // ---- angular neighbor list ----
    if (!self && d <= RCA) {
        const int p = atomicAdd(&s_cnt, 1);
        s_nb[p] = tid;
    }
    __syncthreads();

    // ---- angular terms over unordered neighbor pairs ----
    const int m = s_cnt;
    const int npairs = m * (m - 1) / 2;
    for (int p = tid; p < npairs; p += NATOM) {
        // decode flat pair index -> (jj, kk), jj < kk
        int jj = 0, rem = p;
        while (rem >= m - 1 - jj) { rem -= m - 1 - jj; jj++; }
        const int kk = jj + 1 + rem;
        const int j = s_nb[jj], k = s_nb[kk];

        const float dj = s_d[j], dk = s_d[k];
        const float dot = s_dx[j] * s_dx[k] + s_dy[j] * s_dy[k] + s_dz[j] * s_dz[k];
        float c = 0.95f * dot / (dj * dk);
        c = fminf(0.95f, fmaxf(-0.95f, c));
        const float s = sqrtf(1.0f - c * c);    // sin(arccos(c)) >= 0

        const float base = 2.0f * s_fca[j] * s_fca[k];
        const float davg = 0.5f * (dj + dk);

        float f2[4];
        #pragma unroll
        for (int a = 0; a < 4; a++) {
            const float t = davg - (0.9f + 0.65f * (float)a);
            f2[a] = expf(-8.0f * t * t);
        }
        float f1[8];
        #pragma unroll
        for (int z = 0; z < 8; z++) {
            // ((1 + cos(theta - shz)) / 2)^32, cos(theta-shz) = c*cz + s*sz
            f1[z] = pow32(0.5f * (1.0f + c * c_cz[z] + s * c_sz[z]));
        }

        const int pidx = c_triu[s_spec[j]][s_spec[k]];
        float* dst = &s_ang[pidx * 32];
        #pragma unroll
        for (int a = 0; a < 4; a++) {
            const float bf2 = base * f2[a];
            #pragma unroll
            for (int z = 0; z < 8; z++) {
                atomicAdd(&dst[a * 8 + z], bf2 * f1[z]);
            }
        }
    }
    __syncthreads();

    // ---- write out ----
    float* ob = out + aev_base + (size_t)atom * FEAT;
    ob[tid] = s_rad[tid];
    #pragma unroll
    for (int f = tid; f < ANGF; f += NATOM) ob[RADF + f] = s_ang[f];
    if (write_species && tid == 0) out[atom] = (float)s_spec[i];
}

extern "C" void kernel_launch(void* const* d_in, const int* in_sizes, int n_in,
                              void* d_out, int out_size)
{
    const int*   species = (const int*)d_in[0];
    const float* coords  = (const float*)d_in[1];
    float* out = (float*)d_out;

    // Output is tuple (species, aev) flattened -> 1024 + 393216 elements.
    // Handle aev-only layout defensively.
    const int total_atoms = NMOL * NATOM;       // 1024
    int aev_base = 0, write_species = 0;
    if (out_size >= total_atoms * FEAT + total_atoms) {
        aev_base = total_atoms;
        write_species = 1;
    }

    aev_kernel<<<total_atoms, NATOM>>>(species, coords, out, aev_base, write_species);
}

// round 3
// speedup vs baseline: 3.0731x; 3.0731x over previous
#include <cuda_runtime.h>
#include <math.h>

#define NMOL 16
#define NATOM 64
#define RADF 64         // 4 species * 16 radial shifts
#define ANGF 320        // 10 pairs * 4 SHF_A * 8 SHF_Z
#define FEAT 384
#define RCR 5.2f
#define RCA 3.5f
#define TPB 256
#define PCHUNK 512      // pair chunk size

__constant__ int c_triu[4][4] = {
    {0,1,2,3},
    {1,4,5,6},
    {2,5,7,8},
    {3,6,8,9}
};

// cos/sin of SHF_Z[z] = pi/16 * (1 + 2z), z = 0..7
__constant__ float c_cz[8] = {
     0.980785280403230449f,  0.831469612302545237f,  0.555570233019602225f,
     0.195090322016128268f, -0.195090322016128268f, -0.555570233019602225f,
    -0.831469612302545237f, -0.980785280403230449f
};
__constant__ float c_sz[8] = {
     0.195090322016128268f,  0.555570233019602225f,  0.831469612302545237f,
     0.980785280403230449f,  0.980785280403230449f,  0.831469612302545237f,
     0.555570233019602225f,  0.195090322016128268f
};

__device__ __forceinline__ float pow32(float u) {
    u = fmaxf(u, 0.0f);
    u = u * u;   // ^2
    u = u * u;   // ^4
    u = u * u;   // ^8
    u = u * u;   // ^16
    u = u * u;   // ^32
    return u;
}

__global__ __launch_bounds__(TPB)
void aev_kernel(const int* __restrict__ species,
                const float* __restrict__ coords,
                float* __restrict__ out,
                int aev_base,
                int write_species)
{
    const int atom = blockIdx.x;           // 0 .. NMOL*NATOM-1
    const int n = atom >> 6;
    const int i = atom & 63;
    const int tid = threadIdx.x;

    __shared__ float s_c[NATOM * 3];                       // staged coords (flat)
    __shared__ int   s_spec[NATOM];
    __shared__ float s_dx[NATOM], s_dy[NATOM], s_dz[NATOM];
    __shared__ float s_d[NATOM], s_fca[NATOM], s_fcr[NATOM];
    __shared__ int   s_nb[NATOM];
    __shared__ int   s_wcnt[2];
    __shared__ float s_rad[RADF];
    __shared__ float s_ang[ANGF];
    // per-pair precomputed scalars (chunked)
    __shared__ float pc_c[PCHUNK], pc_s[PCHUNK], pc_b[PCHUNK], pc_g[PCHUNK];
    __shared__ int   pc_p[PCHUNK];

    // ---- stage molecule ----
    if (tid < NATOM * 3) s_c[tid] = coords[(size_t)n * NATOM * 3 + tid];
    if (tid < NATOM)     s_spec[tid] = species[n * NATOM + tid];
    // zero accumulators (384 items / 256 threads)
    if (tid < RADF) s_rad[tid] = 0.0f;
    for (int f = tid; f < ANGF; f += TPB) s_ang[f] = 0.0f;
    __syncthreads();

    // ---- geometry: thread tid<64 is neighbor j ----
    bool isnb = false;
    int  rank = 0;
    if (tid < NATOM) {
        const float dx = s_c[tid * 3 + 0] - s_c[i * 3 + 0];
        const float dy = s_c[tid * 3 + 1] - s_c[i * 3 + 1];
        const float dz = s_c[tid * 3 + 2] - s_c[i * 3 + 2];
        const float d  = sqrtf(dx * dx + dy * dy + dz * dz);
        s_dx[tid] = dx; s_dy[tid] = dy; s_dz[tid] = dz;
        s_d[tid]  = d;
        s_fca[tid] = 0.5f * __cosf((float)M_PI / RCA * d) + 0.5f;
        s_fcr[tid] = 0.5f * __cosf((float)M_PI / RCR * d) + 0.5f;
        isnb = (tid != i) && (d <= RCA);
        const unsigned mask = __ballot_sync(0xffffffffu, isnb);
        rank = __popc(mask & ((1u << (tid & 31)) - 1u));
        if ((tid & 31) == 0) s_wcnt[tid >> 5] = __popc(mask);
    }
    __syncthreads();

    // ---- neighbor-list write (deterministic order) + radial ----
    if (isnb) {
        const int base = (tid >= 32) ? s_wcnt[0] : 0;
        s_nb[base + rank] = tid;
    }
    // radial: (j, r) 2D parallel; r varies across lanes -> low atomic conflict
    #pragma unroll
    for (int k = 0; k < 4; k++) {
        const int item = tid + k * TPB;          // 0..1023
        const int j = item >> 4;
        const int r = item & 15;
        const float d = s_d[j];
        if (j != i && d <= RCR) {
            const float t = d - (0.9f + 0.26875f * (float)r);
            atomicAdd(&s_rad[s_spec[j] * 16 + r],
                      0.25f * __expf(-16.0f * t * t) * s_fcr[j]);
        }
    }
    __syncthreads();

    const int m = s_wcnt[0] + s_wcnt[1];
    const int npairs = m * (m - 1) / 2;

    // ---- angular: chunked (precompute scalars, then feature-parallel accumulate) ----
    const int fth = tid & 31;          // feature within bucket
    const int a   = fth >> 3;
    const int z   = fth & 7;
    const float sha = 0.9f + 0.65f * (float)a;
    const float cz = c_cz[z], sz = c_sz[z];

    for (int c0 = 0; c0 < npairs; c0 += PCHUNK) {
        const int nc = min(PCHUNK, npairs - c0);

        // phase B: per-pair scalars
        for (int q = tid; q < nc; q += TPB) {
            const int p = c0 + q;
            int jj = 0, rem = p;
            while (rem >= m - 1 - jj) { rem -= m - 1 - jj; jj++; }
            const int kk = jj + 1 + rem;
            const int j = s_nb[jj], k = s_nb[kk];

            const float dj = s_d[j], dk = s_d[k];
            const float dot = s_dx[j] * s_dx[k] + s_dy[j] * s_dy[k] + s_dz[j] * s_dz[k];
            float c = __fdividef(0.95f * dot, dj * dk);
            c = fminf(0.95f, fmaxf(-0.95f, c));
            pc_c[q] = c;
            pc_s[q] = sqrtf(1.0f - c * c);
            pc_b[q] = 2.0f * s_fca[j] * s_fca[k];
            pc_g[q] = 0.5f * (dj + dk);
            pc_p[q] = c_triu[s_spec[j]][s_spec[k]];
        }
        __syncthreads();

        // phase C: warp q-loop, lane = feature; all-distinct atomic addresses
        for (int q = tid >> 5; q < nc; q += TPB / 32) {
            const float cth = pc_c[q];
            const float sth = pc_s[q];
            const float t = pc_g[q] - sha;
            const float f2 = __expf(-8.0f * t * t);
            const float f1 = pow32(0.5f * (1.0f + cth * cz + sth * sz));
            atomicAdd(&s_ang[pc_p[q] * 32 + fth], pc_b[q] * f2 * f1);
        }
        __syncthreads();
    }

    // ---- write out ----
    float* ob = out + aev_base + (size_t)atom * FEAT;
    if (tid < RADF) ob[tid] = s_rad[tid];
    for (int f = tid; f < ANGF; f += TPB) ob[RADF + f] = s_ang[f];
    if (write_species && tid == 0) out[atom] = (float)s_spec[i];
}

extern "C" void kernel_launch(void* const* d_in, const int* in_sizes, int n_in,
                              void* d_out, int out_size)
{
    const int*   species = (const int*)d_in[0];
    const float* coords  = (const float*)d_in[1];
    float* out = (float*)d_out;

    const int total_atoms = NMOL * NATOM;       // 1024
    int aev_base = 0, write_species = 0;
    if (out_size >= total_atoms * FEAT + total_atoms) {
        aev_base = total_atoms;
        write_species = 1;
    }

    aev_kernel<<<total_atoms, TPB>>>(species, coords, out, aev_base, write_species);
}